// round 16
// baseline (speedup 1.0000x reference)
#include <cuda_runtime.h>

// Problem constants
#define NB   16        // batches
#define NPB  262144    // elements per batch (512*512)
#define HB   64        // histogram bins
#define HC   32        // fused CTAs per batch (grid 512 -- co-residency proven)
#define HT   128       // threads per CTA

#define KL_EPS 1e-8f
#define WEIGHT 0.1f

// ---------------- device scratch (no allocations allowed) ----------------
__device__ float  g_pmin[NB][HC];
__device__ float  g_pmax[NB][HC];
__device__ float  g_part[NB][2][HC][HB];   // [batch][t=0/p=1][cta][bin]
__device__ double g_hsum[NB][2][HB];       // fp64 reduced histograms
__device__ double g_tot[NB][2];            // fp64 per-(b,p) totals
__device__ unsigned int g_bar;             // monotonic grid-barrier counter (never
                                           // reset; each launch adds exactly NB*HC
                                           // arrivals -> generation is launch-local
                                           // -> CUDA-graph-replay safe)

// ---------------- fused kernel: minmax + grid barrier + soft histograms ----------
// Residency proof (grid barrier REQUIRES all 512 CTAs co-resident):
//   smem ~32.1KB -> <=7 CTAs/SM; __launch_bounds__(128,4) -> >=4 CTAs/SM by regs.
//   floor = 4 * 148 = 592 >= 512. (This exact barrier ran in R15.)
//
// Hist: R14-proven numerics. Gaussian KDE sigma=1 bin, 13-bin symmetric window
// (|d|<=6.5; nearest dropped bin >=6.0 sigma -> truncation ~1e-8, invisible).
// CENTER-OUT recurrence (seed at the max-weight center bin; rounding accumulates
// only toward tails where g ~ 0):
//   up:   g *= r,  r0 = __expf(c-0.5),  r *= e^-1
//   down: g *= q,  q0 = __expf(-c-0.5), q *= e^-1
// Per-thread SMEM histograms hist[bin*HT+tid] -> conflict-free, no atomics.
// Crossbar floor: 13 slots x 8B x 8.39M elem / (148 SM x 128 B/cyc) ~ 26us.
__global__ void __launch_bounds__(HT, 4) k_fused(const float* __restrict__ pred,
                                                 const float* __restrict__ target) {
    __shared__ float hist[HB * HT];   // 32 KB
    __shared__ float slo[4], shi[4];
    __shared__ float s_vmin, s_scale;
    const int b   = blockIdx.y;
    const int c0  = blockIdx.x;
    const int tid = threadIdx.x;
    const float EINV = 0.36787944117144233f;  // e^-1

    // ---- phase A: min/max of this CTA's own target slice (8192 elements) ----
    const float4* tbase = reinterpret_cast<const float4*>(target)
                          + (size_t)b * (NPB / 4) + (size_t)c0 * (NPB / 4 / HC);
    {
        float lo = __int_as_float(0x7f800000);   // +inf
        float hi = __int_as_float(0xff800000);   // -inf
        #pragma unroll
        for (int k = 0; k < (NPB / 4 / HC) / HT; k++) {   // 16 float4 per thread
            float4 v = tbase[k * HT + tid];
            lo = fminf(lo, fminf(fminf(v.x, v.y), fminf(v.z, v.w)));
            hi = fmaxf(hi, fmaxf(fmaxf(v.x, v.y), fmaxf(v.z, v.w)));
        }
        #pragma unroll
        for (int o = 16; o; o >>= 1) {
            lo = fminf(lo, __shfl_xor_sync(0xffffffffu, lo, o));
            hi = fmaxf(hi, __shfl_xor_sync(0xffffffffu, hi, o));
        }
        int w = tid >> 5;
        if ((tid & 31) == 0) { slo[w] = lo; shi[w] = hi; }
        __syncthreads();
        if (tid == 0) {
            lo = fminf(fminf(slo[0], slo[1]), fminf(slo[2], slo[3]));
            hi = fmaxf(fmaxf(shi[0], shi[1]), fmaxf(shi[2], shi[3]));
            g_pmin[b][c0] = lo;
            g_pmax[b][c0] = hi;
            __threadfence();   // publish partials before arriving
        }
    }

    // ---- grid barrier (monotonic counter, replay-safe) ----
    if (tid == 0) {
        unsigned int old = atomicAdd(&g_bar, 1u);
        unsigned int tgt = (old / (NB * HC) + 1u) * (NB * HC);
        while (*(volatile unsigned int*)&g_bar < tgt) { }
        __threadfence();
    }
    __syncthreads();

    // ---- global vmin/scale for this batch (HC=32 partials, warp 0) ----
    if (tid < 32) {
        float lo = *((volatile float*)&g_pmin[b][tid]);
        float hi = *((volatile float*)&g_pmax[b][tid]);
        #pragma unroll
        for (int o = 16; o; o >>= 1) {
            lo = fminf(lo, __shfl_xor_sync(0xffffffffu, lo, o));
            hi = fmaxf(hi, __shfl_xor_sync(0xffffffffu, hi, o));
        }
        if (tid == 0) {
            s_vmin  = lo;
            s_scale = 64.0f / (hi - lo + KL_EPS);
        }
    }
    __syncthreads();

    const float vmin  = s_vmin;
    const float scale = s_scale;
    const float bias  = -vmin * scale;

    // ---- phase B: soft histograms (target then pred) ----
    #pragma unroll 1
    for (int phase = 0; phase < 2; phase++) {
        const float4* base4 = (phase == 0)
            ? tbase
            : reinterpret_cast<const float4*>(pred)
              + (size_t)b * (NPB / 4) + (size_t)c0 * (NPB / 4 / HC);

        #pragma unroll
        for (int j = 0; j < HB; j++) hist[j * HT + tid] = 0.0f;
        __syncthreads();

        #pragma unroll 1
        for (int i = tid; i < NPB / 4 / HC; i += HT) {
            float4 v = base4[i];
            float xs[4] = {v.x, v.y, v.z, v.w};
            #pragma unroll
            for (int e = 0; e < 4; e++) {
                float u  = fmaf(xs[e], scale, bias);   // position in bin units
                float jf = floorf(u);
                int   jc = (int)jf;                    // center bin (contains u)
                float c  = u - jf - 0.5f;              // offset from center bin's center
                float g0 = __expf(-0.5f * c * c);
                float r  = __expf(c - 0.5f);           // upward ratio seed
                float q  = __expf(-c - 0.5f);          // downward ratio seed

                if ((unsigned)jc < (unsigned)HB) hist[jc * HT + tid] += g0;
                float gu = g0, gd = g0;
                #pragma unroll
                for (int m = 1; m <= 6; m++) {
                    gu *= r;
                    int ju = jc + m;
                    if ((unsigned)ju < (unsigned)HB) hist[ju * HT + tid] += gu;
                    r *= EINV;
                    gd *= q;
                    int jd = jc - m;
                    if ((unsigned)jd < (unsigned)HB) hist[jd * HT + tid] += gd;
                    q *= EINV;
                }
            }
        }
        __syncthreads();

        // reduce 128 per-thread slices -> 64 bins (rotated, conflict-free,
        // 4 split accumulators -- R14-proven rounding behavior)
        if (tid < HB) {
            const int bin = tid;
            float s0 = 0.f, s1 = 0.f, s2 = 0.f, s3 = 0.f;
            #pragma unroll 4
            for (int s = 0; s < HT; s += 4) {
                s0 += hist[bin * HT + ((s + 0 + bin) & (HT - 1))];
                s1 += hist[bin * HT + ((s + 1 + bin) & (HT - 1))];
                s2 += hist[bin * HT + ((s + 2 + bin) & (HT - 1))];
                s3 += hist[bin * HT + ((s + 3 + bin) & (HT - 1))];
            }
            g_part[b][phase][c0][bin] = (s0 + s1) + (s2 + s3);
        }
        __syncthreads();
    }
}

// ---------------- kernel 2: fp64 cross-CTA reduce (32 CTAs, parallel) ----------
// R13 lesson applied correctly: fp64 is fine when spread across SMs. Each CTA
// owns one (b,p): 64 threads, thread j sums the HC=32 partials of bin j in
// fp64 (2 split accumulators for latency), then an fp64 warp/CTA reduction for
// the total. Fixed dataflow -> deterministic. Exact to ~1e-16 -> the tail no
// longer contributes to rel_err at all.
__global__ void __launch_bounds__(HB) k_reduce() {
    __shared__ double wtot[2];
    const int b = blockIdx.x >> 1;
    const int p = blockIdx.x & 1;
    const int j = threadIdx.x;

    const float* src = &g_part[b][p][0][0];
    double sa = 0.0, sb = 0.0;
    #pragma unroll
    for (int c = 0; c < HC; c += 2) {
        sa += (double)src[c * HB + j];
        sb += (double)src[(c + 1) * HB + j];
    }
    double s = sa + sb;
    g_hsum[b][p][j] = s;

    // total over 64 bins: fp64 butterfly within each warp, combine 2 warps
    double t = s;
    #pragma unroll
    for (int o = 16; o; o >>= 1) t += __shfl_xor_sync(0xffffffffu, t, o);
    if ((j & 31) == 0) wtot[j >> 5] = t;
    __syncthreads();
    if (j == 0) g_tot[b][p] = wtot[0] + wtot[1];
}

// ---------------- kernel 3: KL + output (1 CTA, tiny) ----------------
// 32 fp64 reciprocals + one DMUL per (b,bin); logs in fp32 (per-bin log
// rounding is independent across bins -> ~5e-5 final contribution).
__global__ void __launch_bounds__(1024) k_fin(float* __restrict__ out) {
    __shared__ double recp[NB][2];
    __shared__ float wsum[32];
    const int tid  = threadIdx.x;
    const int lane = tid & 31;
    const int w    = tid >> 5;

    if (tid < NB * 2)
        recp[tid >> 1][tid & 1] = 1.0 / (g_tot[tid >> 1][tid & 1] + (double)KL_EPS);
    __syncthreads();

    const int b = tid >> 6;
    const int j = tid & (HB - 1);
    double tp = g_hsum[b][0][j] * recp[b][0];
    double pp = g_hsum[b][1][j] * recp[b][1];
    float argT = (float)(tp + (double)KL_EPS);
    float argP = (float)(pp + (double)KL_EPS);
    float term = (float)tp * (logf(argT) - logf(argP));

    #pragma unroll
    for (int o = 16; o; o >>= 1) term += __shfl_xor_sync(0xffffffffu, term, o);
    if (lane == 0) wsum[w] = term;
    __syncthreads();
    if (w == 0) {
        float v = wsum[lane];
        #pragma unroll
        for (int o = 16; o; o >>= 1) v += __shfl_xor_sync(0xffffffffu, v, o);
        if (lane == 0) out[0] = WEIGHT * (v / (float)NB);
    }
}

// ---------------- launch ----------------
extern "C" void kernel_launch(void* const* d_in, const int* in_sizes, int n_in,
                              void* d_out, int out_size) {
    const float* pred   = (const float*)d_in[0];
    const float* target = (const float*)d_in[1];
    float* out = (float*)d_out;

    k_fused <<<dim3(HC, NB), HT>>>(pred, target);
    k_reduce<<<NB * 2, HB>>>();
    k_fin   <<<1, 1024>>>(out);
}

// round 17
// speedup vs baseline: 1.1335x; 1.1335x over previous
#include <cuda_runtime.h>

// Problem constants
#define NB   16        // batches
#define NPB  262144    // elements per batch (512*512)
#define HB   64        // histogram bins
#define HC   64        // hist CTAs per batch (grid 1024 -> 6-7 CTAs/SM: hist loop is
                       // issue/latency-bound and NEEDS this occupancy; R16 proved
                       // HC=32 costs +18us)
#define HT   128       // hist threads per CTA
#define MC   64        // minmax CTAs per batch (R13-profiled 6.56us)

#define KL_EPS 1e-8f
#define WEIGHT 0.1f

// ---------------- device scratch (no allocations allowed) ----------------
__device__ float  g_pmin[NB][MC];
__device__ float  g_pmax[NB][MC];
__device__ float  g_part[NB][2][HC][HB];   // [batch][t=0/p=1][cta][bin]
__device__ double g_hsum[NB][2][HB];       // fp64 reduced histograms
__device__ double g_tot[NB][2];            // fp64 per-(b,p) totals

// ---------------- kernel 1: per-batch min/max partials (no atomics) ----------------
// grid (MC, NB) = 1024 CTAs x 256 threads, 4 float4 each (R13 version, 6.56us).
__global__ void __launch_bounds__(256) k_minmax(const float* __restrict__ target) {
    const int b = blockIdx.y;
    const float4* base = reinterpret_cast<const float4*>(target)
                         + (size_t)b * (NPB / 4) + (size_t)blockIdx.x * (NPB / 4 / MC);
    float lo = __int_as_float(0x7f800000);   // +inf
    float hi = __int_as_float(0xff800000);   // -inf
    #pragma unroll
    for (int k = 0; k < (NPB / 4 / MC) / 256; k++) {
        float4 v = base[k * 256 + threadIdx.x];
        lo = fminf(lo, fminf(fminf(v.x, v.y), fminf(v.z, v.w)));
        hi = fmaxf(hi, fmaxf(fmaxf(v.x, v.y), fmaxf(v.z, v.w)));
    }
    #pragma unroll
    for (int o = 16; o; o >>= 1) {
        lo = fminf(lo, __shfl_xor_sync(0xffffffffu, lo, o));
        hi = fmaxf(hi, __shfl_xor_sync(0xffffffffu, hi, o));
    }
    __shared__ float slo[8], shi[8];
    int w = threadIdx.x >> 5;
    if ((threadIdx.x & 31) == 0) { slo[w] = lo; shi[w] = hi; }
    __syncthreads();
    if (threadIdx.x == 0) {
        #pragma unroll
        for (int k = 1; k < 8; k++) { lo = fminf(lo, slo[k]); hi = fmaxf(hi, shi[k]); }
        g_pmin[b][blockIdx.x] = lo;
        g_pmax[b][blockIdx.x] = hi;
    }
}

// ---------------- kernel 2: soft histograms (R14-proven numerics, HC=64) ----------
// Gaussian KDE sigma=1 bin, 13-bin symmetric window (|d|<=6.5).
// CENTER-OUT recurrence, seeded at the max-weight center bin with __expf
// (2-ulp seed error is symmetric in the in-bin offset -> cancels between the
// two normalized hists in the KL):
//   up:   g *= r,  r0 = __expf(c-0.5),  r *= e^-1
//   down: g *= q,  q0 = __expf(-c-0.5), q *= e^-1
// Per-thread SMEM histograms hist[bin*HT+tid] -> conflict-free, no atomics.
__global__ void __launch_bounds__(HT) k_hist(const float* __restrict__ pred,
                                             const float* __restrict__ target) {
    __shared__ float hist[HB * HT];   // 32 KB
    __shared__ float red[2][HB];
    __shared__ float s_vmin, s_scale;
    const int b   = blockIdx.y;
    const int c0  = blockIdx.x;
    const int tid = threadIdx.x;
    const float EINV = 0.36787944117144233f;  // e^-1

    if (tid < 32) {
        float lo = fminf(g_pmin[b][tid], g_pmin[b][tid + 32]);
        float hi = fmaxf(g_pmax[b][tid], g_pmax[b][tid + 32]);
        #pragma unroll
        for (int o = 16; o; o >>= 1) {
            lo = fminf(lo, __shfl_xor_sync(0xffffffffu, lo, o));
            hi = fmaxf(hi, __shfl_xor_sync(0xffffffffu, hi, o));
        }
        if (tid == 0) {
            s_vmin  = lo;
            s_scale = 64.0f / (hi - lo + KL_EPS);
        }
    }

    #pragma unroll 1
    for (int phase = 0; phase < 2; phase++) {
        const float* src = (phase == 0) ? target : pred;
        const float4* base = reinterpret_cast<const float4*>(src)
                             + (size_t)b * (NPB / 4) + (size_t)c0 * (NPB / 4 / HC);

        #pragma unroll
        for (int j = 0; j < HB; j++) hist[j * HT + tid] = 0.0f;
        __syncthreads();

        const float vmin  = s_vmin;
        const float scale = s_scale;
        const float bias  = -vmin * scale;

        #pragma unroll 1
        for (int i = tid; i < NPB / 4 / HC; i += HT) {
            float4 v = base[i];
            float xs[4] = {v.x, v.y, v.z, v.w};
            #pragma unroll
            for (int e = 0; e < 4; e++) {
                float u  = fmaf(xs[e], scale, bias);   // position in bin units
                float jf = floorf(u);
                int   jc = (int)jf;                    // center bin (contains u)
                float c  = u - jf - 0.5f;              // offset from center bin's center
                float g0 = __expf(-0.5f * c * c);
                float r  = __expf(c - 0.5f);           // upward ratio seed
                float q  = __expf(-c - 0.5f);          // downward ratio seed

                if ((unsigned)jc < (unsigned)HB) hist[jc * HT + tid] += g0;
                float gu = g0, gd = g0;
                #pragma unroll
                for (int m = 1; m <= 6; m++) {
                    gu *= r;
                    int ju = jc + m;
                    if ((unsigned)ju < (unsigned)HB) hist[ju * HT + tid] += gu;
                    r *= EINV;
                    gd *= q;
                    int jd = jc - m;
                    if ((unsigned)jd < (unsigned)HB) hist[jd * HT + tid] += gd;
                    q *= EINV;
                }
            }
        }
        __syncthreads();

        // reduce 128 per-thread slices -> 64 bins, ALL 128 threads active:
        // thread (h, bin) sums slices [h*64, h*64+64) for its bin with 4 split
        // accumulators (depth 16 -> lower rounding than R14), rotated by bin
        // -> conflict-free. Then halves combined in fixed order.
        {
            const int bin = tid & (HB - 1);
            const int h   = tid >> 6;
            float s0 = 0.f, s1 = 0.f, s2 = 0.f, s3 = 0.f;
            #pragma unroll 4
            for (int s = 0; s < 64; s += 4) {
                int base_s = h * 64 + s;
                s0 += hist[bin * HT + ((base_s + 0 + bin) & (HT - 1))];
                s1 += hist[bin * HT + ((base_s + 1 + bin) & (HT - 1))];
                s2 += hist[bin * HT + ((base_s + 2 + bin) & (HT - 1))];
                s3 += hist[bin * HT + ((base_s + 3 + bin) & (HT - 1))];
            }
            red[h][bin] = (s0 + s1) + (s2 + s3);
        }
        __syncthreads();
        if (tid < HB)
            g_part[b][phase][c0][tid] = red[0][tid] + red[1][tid];
        __syncthreads();
    }
}

// ---------------- kernel 3: fp64 cross-CTA reduce (32 CTAs, parallel) ----------
// fp64 spread across 32 SMs is cheap (R13 lesson: it's fp64 on ONE SM that
// kills). Exact to ~1e-16 -> tail contributes nothing to rel_err.
__global__ void __launch_bounds__(HB) k_reduce() {
    __shared__ double wtot[2];
    const int b = blockIdx.x >> 1;
    const int p = blockIdx.x & 1;
    const int j = threadIdx.x;

    const float* src = &g_part[b][p][0][0];
    double sa = 0.0, sb = 0.0;
    #pragma unroll
    for (int c = 0; c < HC; c += 2) {
        sa += (double)src[c * HB + j];
        sb += (double)src[(c + 1) * HB + j];
    }
    double s = sa + sb;
    g_hsum[b][p][j] = s;

    double t = s;
    #pragma unroll
    for (int o = 16; o; o >>= 1) t += __shfl_xor_sync(0xffffffffu, t, o);
    if ((j & 31) == 0) wtot[j >> 5] = t;
    __syncthreads();
    if (j == 0) g_tot[b][p] = wtot[0] + wtot[1];
}

// ---------------- kernel 4: KL + output (1 CTA, tiny) ----------------
__global__ void __launch_bounds__(1024) k_fin(float* __restrict__ out) {
    __shared__ double recp[NB][2];
    __shared__ float wsum[32];
    const int tid  = threadIdx.x;
    const int lane = tid & 31;
    const int w    = tid >> 5;

    if (tid < NB * 2)
        recp[tid >> 1][tid & 1] = 1.0 / (g_tot[tid >> 1][tid & 1] + (double)KL_EPS);
    __syncthreads();

    const int b = tid >> 6;
    const int j = tid & (HB - 1);
    double tp = g_hsum[b][0][j] * recp[b][0];
    double pp = g_hsum[b][1][j] * recp[b][1];
    float argT = (float)(tp + (double)KL_EPS);
    float argP = (float)(pp + (double)KL_EPS);
    float term = (float)tp * (logf(argT) - logf(argP));

    #pragma unroll
    for (int o = 16; o; o >>= 1) term += __shfl_xor_sync(0xffffffffu, term, o);
    if (lane == 0) wsum[w] = term;
    __syncthreads();
    if (w == 0) {
        float v = wsum[lane];
        #pragma unroll
        for (int o = 16; o; o >>= 1) v += __shfl_xor_sync(0xffffffffu, v, o);
        if (lane == 0) out[0] = WEIGHT * (v / (float)NB);
    }
}

// ---------------- launch ----------------
extern "C" void kernel_launch(void* const* d_in, const int* in_sizes, int n_in,
                              void* d_out, int out_size) {
    const float* pred   = (const float*)d_in[0];
    const float* target = (const float*)d_in[1];
    float* out = (float*)d_out;

    k_minmax<<<dim3(MC, NB), 256>>>(target);
    k_hist  <<<dim3(HC, NB), HT>>>(pred, target);
    k_reduce<<<NB * 2, HB>>>();
    k_fin   <<<1, 1024>>>(out);
}